// round 1
// baseline (speedup 1.0000x reference)
#include <cuda_runtime.h>
#include <cstdint>

#define BATCH   8
#define NANCH   25200
#define NCH     85
#define TOPK    1000
#define KPAD    1024
#define CONF_TH 0.25f
#define IOU_TH  0.45f
#define MAX_WH  4096.0f

// ---------------- scratch (device globals; no allocation) ----------------
__device__ float    g_score[BATCH * NANCH];
__device__ int      g_cls[BATCH * NANCH];
__device__ int      g_topidx[BATCH * KPAD];
__device__ float    g_topscore[BATCH * KPAD];
__device__ float4   g_boxk[BATCH * TOPK];
__device__ float4   g_offk[BATCH * TOPK];
__device__ float    g_clsf[BATCH * TOPK];
__device__ unsigned g_bitmat[BATCH * TOPK * 32];

// ---------------- K1: score = obj * max(cls), masked; argmax class ----------------
__global__ void k_score(const float* __restrict__ x) {
    int a    = blockIdx.x * 8 + (threadIdx.x >> 5);   // anchor id (global over batch*N)
    int lane = threadIdx.x & 31;
    const float* p = x + (size_t)a * NCH;
    float v0 = p[lane];
    float v1 = p[32 + lane];
    float v2 = (lane < 21) ? p[64 + lane] : 0.0f;
    float obj = __shfl_sync(0xffffffffu, v0, 4);

    float best = __int_as_float(0xff800000);  // -inf
    int   bi   = 1 << 30;
    if (lane >= 5)              { best = v0; bi = lane - 5;  }   // cls 0..26
    if (v1 > best)              { best = v1; bi = 27 + lane; }   // cls 27..58
    if (lane < 21 && v2 > best) { best = v2; bi = 59 + lane; }   // cls 59..79
    // warp reduce: max value, ties -> lowest class index (matches jnp.argmax)
    #pragma unroll
    for (int off = 16; off; off >>= 1) {
        float ov = __shfl_down_sync(0xffffffffu, best, off);
        int   oi = __shfl_down_sync(0xffffffffu, bi, off);
        if (ov > best || (ov == best && oi < bi)) { best = ov; bi = oi; }
    }
    if (lane == 0) {
        float sc = __fmul_rn(obj, best);
        g_score[a] = (sc > CONF_TH) ? sc : -1.0f;
        g_cls[a]   = bi;
    }
}

// ---------------- K2: exact top-1000 per batch ----------------
// 64-bit composite key = (monotone float bits << 32) | ~index  -> all keys distinct,
// descending sort == (score desc, index asc) == jax.lax.top_k ordering.
// Radix-select (8 byte passes) for the exact 1000th key, compact, bitonic-sort 1024.
#define K2_SMEM 111064
__global__ void __launch_bounds__(1024) k_topk() {
    const int b   = blockIdx.x;
    const int tid = threadIdx.x;
    extern __shared__ unsigned char smraw[];
    unsigned* enc  = (unsigned*)smraw;            // [NANCH]  -> 100800 B
    unsigned* hist = enc + NANCH;                 // [256]
    unsigned* scn  = hist + 256;                  // [256]
    unsigned long long* s_prefix = (unsigned long long*)(smraw + 102848);
    unsigned* s_krem = (unsigned*)(smraw + 102856);
    unsigned* s_knew = (unsigned*)(smraw + 102860);
    unsigned* s_cnt  = (unsigned*)(smraw + 102864);
    unsigned long long* outk = (unsigned long long*)(smraw + 102872); // [1024]

    // load + monotone-encode scores
    #pragma unroll
    for (int it = 0; it < 25; ++it) {
        int i = tid + it * 1024;
        if (i < NANCH) {
            unsigned u = __float_as_uint(g_score[b * NANCH + i]);
            enc[i] = (u & 0x80000000u) ? ~u : (u | 0x80000000u);
        }
    }
    if (tid == 0) { *s_prefix = 0ull; *s_krem = TOPK; *s_cnt = 0u; }
    __syncthreads();

    // 8 radix passes over the 64-bit composite key
    for (int p = 7; p >= 0; --p) {
        if (tid < 256) hist[tid] = 0u;
        __syncthreads();
        unsigned long long pref = *s_prefix;
        unsigned kr = *s_krem;
        for (int it = 0; it < 25; ++it) {
            int i = tid + it * 1024;
            unsigned byte = 0xffffffffu;
            if (i < NANCH) {
                unsigned long long key =
                    ((unsigned long long)enc[i] << 32) | (unsigned)(~(unsigned)i);
                bool match = (p == 7) || ((key >> (8 * (p + 1))) == pref);
                if (match) byte = (unsigned)((key >> (8 * p)) & 255u);
            }
            unsigned mm = __match_any_sync(0xffffffffu, byte);
            if (byte != 0xffffffffu) {
                int leader = __ffs(mm) - 1;
                if ((tid & 31) == leader) atomicAdd(&hist[byte], (unsigned)__popc(mm));
            }
        }
        __syncthreads();
        // inclusive suffix sums over 256 buckets
        if (tid < 256) scn[tid] = hist[tid];
        __syncthreads();
        for (int d = 1; d < 256; d <<= 1) {
            unsigned v = 0;
            if (tid < 256 && tid + d < 256) v = scn[tid + d];
            __syncthreads();
            if (tid < 256) scn[tid] += v;
            __syncthreads();
        }
        if (tid < 256) {
            unsigned tot = scn[tid];
            unsigned gt  = tot - hist[tid];     // count strictly greater than bucket tid
            if (gt < kr && kr <= tot) {         // exactly one bucket satisfies this
                *s_prefix = (pref << 8) | (unsigned long long)tid;
                *s_knew   = kr - gt;
            }
        }
        __syncthreads();
        if (tid == 0) *s_krem = *s_knew;
        __syncthreads();
    }

    // compact: keys are distinct -> exactly TOPK keys satisfy key >= T
    unsigned long long T = *s_prefix;
    for (int it = 0; it < 25; ++it) {
        int i = tid + it * 1024;
        if (i < NANCH) {
            unsigned long long key =
                ((unsigned long long)enc[i] << 32) | (unsigned)(~(unsigned)i);
            if (key >= T) {
                unsigned pos = atomicAdd(s_cnt, 1u);
                if (pos < KPAD) outk[pos] = key;
            }
        }
    }
    __syncthreads();
    unsigned cnt = *s_cnt;
    if (tid >= cnt) outk[tid] = 0ull;   // pad
    __syncthreads();

    // bitonic sort 1024, descending
    for (unsigned kk = 2; kk <= 1024; kk <<= 1) {
        for (unsigned j = kk >> 1; j > 0; j >>= 1) {
            unsigned i = (unsigned)tid, ixj = i ^ j;
            if (ixj > i) {
                unsigned long long a = outk[i], bb = outk[ixj];
                bool desc = ((i & kk) == 0);
                if (desc ? (a < bb) : (a > bb)) { outk[i] = bb; outk[ixj] = a; }
            }
            __syncthreads();
        }
    }

    if (tid < TOPK) {
        unsigned long long key = outk[tid];
        unsigned e = (unsigned)(key >> 32);
        unsigned u = (e & 0x80000000u) ? (e ^ 0x80000000u) : ~e;
        g_topscore[b * KPAD + tid] = __uint_as_float(u);
        g_topidx[b * KPAD + tid]   = (int)(~(unsigned)(key & 0xffffffffull));
    } else {
        g_topscore[b * KPAD + tid] = -1.0f;
        g_topidx[b * KPAD + tid]   = 0;
    }
}

// ---------------- K3a: gather boxes, xywh->xyxy, class offsets ----------------
__global__ void k_boxes(const float* __restrict__ x) {
    int t = blockIdx.x * blockDim.x + threadIdx.x;
    if (t >= BATCH * TOPK) return;
    int b = t / TOPK, r = t - b * TOPK;
    int idx = g_topidx[b * KPAD + r];
    const float* p = x + ((size_t)b * NANCH + idx) * NCH;
    float cx = p[0], cy = p[1], w = p[2], h = p[3];
    float hw = __fmul_rn(w, 0.5f), hh = __fmul_rn(h, 0.5f);
    float x1 = __fsub_rn(cx, hw), y1 = __fsub_rn(cy, hh);
    float x2 = __fadd_rn(cx, hw), y2 = __fadd_rn(cy, hh);
    float cf = (float)g_cls[b * NANCH + idx];
    float o  = __fmul_rn(cf, MAX_WH);
    g_boxk[t] = make_float4(x1, y1, x2, y2);
    g_offk[t] = make_float4(__fadd_rn(x1, o), __fadd_rn(y1, o),
                            __fadd_rn(x2, o), __fadd_rn(y2, o));
    g_clsf[t] = cf;
}

// ---------------- K3b: IoU > thresh bit matrix (1000x1000 bits / batch) ----------------
__global__ void k_iou() {
    int row  = blockIdx.x * 8 + (threadIdx.x >> 5);  // [0, BATCH*TOPK)
    int lane = threadIdx.x & 31;
    int b = row / TOPK, i = row - b * TOPK;
    float4 bi = g_offk[b * TOPK + i];
    float ai = __fmul_rn(__fsub_rn(bi.z, bi.x), __fsub_rn(bi.w, bi.y));
    unsigned word = 0;
    int jbase = lane * 32;
    #pragma unroll 4
    for (int jj = 0; jj < 32; ++jj) {
        int j = jbase + jj;
        if (j < TOPK && j != i) {
            float4 bj = g_offk[b * TOPK + j];
            float ltx = fmaxf(bi.x, bj.x), lty = fmaxf(bi.y, bj.y);
            float rbx = fminf(bi.z, bj.z), rby = fminf(bi.w, bj.w);
            float ww = fmaxf(__fsub_rn(rbx, ltx), 0.0f);
            float hh = fmaxf(__fsub_rn(rby, lty), 0.0f);
            float inter = __fmul_rn(ww, hh);
            float aj = __fmul_rn(__fsub_rn(bj.z, bj.x), __fsub_rn(bj.w, bj.y));
            float denom = __fadd_rn(__fsub_rn(__fadd_rn(ai, aj), inter), 1e-9f);
            float iou = __fdiv_rn(inter, denom);
            if (iou > IOU_TH) word |= (1u << jj);
        }
    }
    g_bitmat[(b * TOPK + i) * 32 + lane] = word;
}

// ---------------- K4: sequential greedy scan + output ----------------
#define K4_SMEM ((TOPK * 32 + 32) * 4)
__global__ void __launch_bounds__(1024) k_scan(float* __restrict__ out) {
    const int b   = blockIdx.x;
    const int tid = threadIdx.x;
    extern __shared__ unsigned sm[];
    unsigned* rows  = sm;             // [TOPK*32]
    unsigned* keepw = sm + TOPK * 32; // [32]
    for (int t = tid; t < TOPK * 32; t += 1024)
        rows[t] = g_bitmat[b * TOPK * 32 + t];
    __syncthreads();

    if (tid < 32) {
        int V = 0;
        if (tid == 0) {  // valid mask is a prefix (scores sorted desc)
            int lo = 0, hi = TOPK;
            while (lo < hi) {
                int mid = (lo + hi) >> 1;
                if (g_topscore[b * KPAD + mid] > CONF_TH) lo = mid + 1; else hi = mid;
            }
            V = lo;
        }
        V = __shfl_sync(0xffffffffu, V, 0);
        unsigned supp = 0, kw = 0;    // 32 bits per lane: lane l owns boxes [32l,32l+32)
        for (int i = 0; i < V; ++i) {
            unsigned rw = rows[i * 32 + tid];                 // speculative prefetch
            int w = i >> 5, bit = i & 31;
            unsigned swrd = __shfl_sync(0xffffffffu, supp, w);
            if (!((swrd >> bit) & 1u)) {                      // keep i
                supp |= rw;
                if (tid == w) kw |= (1u << bit);
            }
        }
        keepw[tid] = kw;
    }
    __syncthreads();

    for (int r = tid; r < TOPK; r += 1024) {
        bool keep = (keepw[r >> 5] >> (r & 31)) & 1u;
        float4 bx = g_boxk[b * TOPK + r];
        float sc  = g_topscore[b * KPAD + r];
        float cf  = g_clsf[b * TOPK + r];
        if (!keep) { bx = make_float4(0.f, 0.f, 0.f, 0.f); sc = 0.f; cf = 0.f; }
        float* o = out + ((size_t)b * TOPK + r) * 6;
        o[0] = bx.x; o[1] = bx.y; o[2] = bx.z; o[3] = bx.w; o[4] = sc; o[5] = cf;
    }
}

// ---------------- launcher ----------------
extern "C" void kernel_launch(void* const* d_in, const int* in_sizes, int n_in,
                              void* d_out, int out_size) {
    (void)in_sizes; (void)n_in; (void)out_size;
    const float* x = (const float*)d_in[0];
    float* out = (float*)d_out;
    cudaFuncSetAttribute(k_topk, cudaFuncAttributeMaxDynamicSharedMemorySize, K2_SMEM);
    cudaFuncSetAttribute(k_scan, cudaFuncAttributeMaxDynamicSharedMemorySize, K4_SMEM);

    k_score<<<(BATCH * NANCH) / 8, 256>>>(x);          // 25200 blocks, 1 warp/anchor
    k_topk <<<BATCH, 1024, K2_SMEM>>>();
    k_boxes<<<(BATCH * TOPK + 255) / 256, 256>>>(x);
    k_iou  <<<(BATCH * TOPK) / 8, 256>>>();
    k_scan <<<BATCH, 1024, K4_SMEM>>>(out);
}

// round 2
// speedup vs baseline: 1.1652x; 1.1652x over previous
#include <cuda_runtime.h>
#include <cstdint>

#define BATCH   8
#define NANCH   25200
#define NCH     85
#define TOPK    1000
#define KPAD    1024
#define CONF_TH 0.25f
#define IOU_TH  0.45f
#define MAX_WH  4096.0f
#define CAP     2048

// ---------------- scratch (device globals; no allocation) ----------------
__device__ float    g_score[BATCH * NANCH];
__device__ int      g_cls[BATCH * NANCH];
__device__ int      g_topidx[BATCH * KPAD];
__device__ float    g_topscore[BATCH * KPAD];
__device__ float4   g_boxk[BATCH * KPAD];
__device__ float4   g_offk[BATCH * KPAD];
__device__ float    g_area[BATCH * KPAD];
__device__ float    g_clsf[BATCH * KPAD];
__device__ unsigned g_bitmat[BATCH * TOPK * 32];

// ---------------- K1: score = obj * max(cls), masked; argmax class ----------------
__global__ void k_score(const float* __restrict__ x) {
    int a    = blockIdx.x * 8 + (threadIdx.x >> 5);
    int lane = threadIdx.x & 31;
    const float* p = x + (size_t)a * NCH;
    float v0 = p[lane];
    float v1 = p[32 + lane];
    float v2 = (lane < 21) ? p[64 + lane] : 0.0f;
    float obj = __shfl_sync(0xffffffffu, v0, 4);

    float best = __int_as_float(0xff800000);
    int   bi   = 1 << 30;
    if (lane >= 5)              { best = v0; bi = lane - 5;  }
    if (v1 > best)              { best = v1; bi = 27 + lane; }
    if (lane < 21 && v2 > best) { best = v2; bi = 59 + lane; }
    #pragma unroll
    for (int off = 16; off; off >>= 1) {
        float ov = __shfl_down_sync(0xffffffffu, best, off);
        int   oi = __shfl_down_sync(0xffffffffu, bi, off);
        if (ov > best || (ov == best && oi < bi)) { best = ov; bi = oi; }
    }
    if (lane == 0) {
        float sc = __fmul_rn(obj, best);
        g_score[a] = (sc > CONF_TH) ? sc : -1.0f;
        g_cls[a]   = bi;
    }
}

// ---------------- K2: exact top-1000 per batch (11-bit radix + compaction) ----------------
// key = (monotone(score) << 32) | ~index  -> distinct keys, desc order == jax.lax.top_k
#define SM_CAND   0
#define SM_CAND2  16384
#define SM_OUTK   32768
#define SM_PREFIX 40960
#define SM_ENC    40968
#define SM_HIST   141768
#define SM_SCN    149960
#define SM_CTRL   158152
#define K2_SMEM   158200

__global__ void __launch_bounds__(1024) k_topk() {
    const int b   = blockIdx.x;
    const int tid = threadIdx.x;
    extern __shared__ unsigned char smraw[];
    unsigned long long* cand   = (unsigned long long*)(smraw + SM_CAND);
    unsigned long long* cand2  = (unsigned long long*)(smraw + SM_CAND2);
    unsigned long long* outk   = (unsigned long long*)(smraw + SM_OUTK);
    unsigned long long* s_pref = (unsigned long long*)(smraw + SM_PREFIX);
    unsigned*           enc    = (unsigned*)(smraw + SM_ENC);
    unsigned*           hist   = (unsigned*)(smraw + SM_HIST);
    unsigned*           scn    = (unsigned*)(smraw + SM_SCN);
    unsigned*           ctrl   = (unsigned*)(smraw + SM_CTRL);
    // ctrl: [0]=need [1]=count [2]=bucket [3]=cnt

    const int shifts_[6] = {53, 42, 31, 20, 9, 0};
    const int widths_[6] = {11, 11, 11, 11, 11, 9};

    if (tid == 0) { *s_pref = 0ull; ctrl[0] = TOPK; ctrl[1] = NANCH; }
    __syncthreads();

    int mode = 0;           // 0 = full array, 1 = compacted candidate list
    unsigned C = 0;
    unsigned long long T64 = 0;
    int have_T = 0;
    unsigned long long* csrc = cand;
    unsigned long long* cdst = cand2;

    for (int lev = 0; lev < 6; ++lev) {
        unsigned need = ctrl[0], count = ctrl[1];
        unsigned long long prefix = *s_pref;
        if (lev > 0) {
            int psh = shifts_[lev - 1];
            if (need == count) { T64 = prefix << psh; have_T = 1; break; }
            if (mode == 0 && count <= CAP) {
                // compact matching elements into cand list
                if (tid == 0) ctrl[3] = 0;
                __syncthreads();
                #pragma unroll
                for (int it = 0; it < 25; ++it) {
                    int i = tid + it * 1024;
                    if (i < NANCH) {
                        unsigned long long key =
                            ((unsigned long long)enc[i] << 32) | (unsigned)(~(unsigned)i);
                        if ((key >> psh) == prefix) {
                            unsigned pos = atomicAdd(&ctrl[3], 1u);
                            if (pos < CAP) cand[pos] = key;
                        }
                    }
                }
                __syncthreads();
                C = count; mode = 1; csrc = cand; cdst = cand2;
            }
        }
        int sh = shifts_[lev], wd = widths_[lev];
        unsigned dmask = (1u << wd) - 1u;
        int psh = (lev > 0) ? shifts_[lev - 1] : 0;

        hist[tid] = 0u; hist[tid + 1024] = 0u;
        __syncthreads();

        if (mode == 1) {
            for (unsigned j = tid; j < C; j += 1024) {
                unsigned d = (unsigned)((csrc[j] >> sh) & dmask);
                atomicAdd(&hist[d], 1u);
            }
        } else {
            #pragma unroll
            for (int it = 0; it < 25; ++it) {
                int i = tid + it * 1024;
                unsigned d = 0xffffffffu;
                if (i < NANCH) {
                    unsigned e;
                    if (lev == 0) {
                        unsigned u = __float_as_uint(g_score[b * NANCH + i]);
                        e = (u & 0x80000000u) ? ~u : (u | 0x80000000u);
                        enc[i] = e;
                        d = e >> 21;   // top 11 bits of key
                    } else {
                        e = enc[i];
                        unsigned long long key =
                            ((unsigned long long)e << 32) | (unsigned)(~(unsigned)i);
                        if ((key >> psh) == prefix)
                            d = (unsigned)((key >> sh) & dmask);
                    }
                }
                unsigned mm = __match_any_sync(0xffffffffu, d);
                if (d != 0xffffffffu) {
                    if ((tid & 31) == (__ffs(mm) - 1))
                        atomicAdd(&hist[d], (unsigned)__popc(mm));
                }
            }
        }
        __syncthreads();

        // inclusive suffix sum over 2048 buckets
        scn[tid] = hist[tid]; scn[tid + 1024] = hist[tid + 1024];
        __syncthreads();
        for (int d = 1; d < 2048; d <<= 1) {
            unsigned v0 = (tid + d < 2048) ? scn[tid + d] : 0u;
            unsigned v1 = (tid + 1024 + d < 2048) ? scn[tid + 1024 + d] : 0u;
            __syncthreads();
            scn[tid] += v0; scn[tid + 1024] += v1;
            __syncthreads();
        }
        // select boundary bucket
        #pragma unroll
        for (int q = 0; q < 2; ++q) {
            int d = tid + q * 1024;
            unsigned tot = scn[d], gt = tot - hist[d];
            if (gt < need && need <= tot) ctrl[2] = (unsigned)d;
        }
        __syncthreads();
        if (tid == 0) {
            unsigned bucket = ctrl[2];
            unsigned gt = scn[bucket] - hist[bucket];
            *s_pref = (prefix << wd) | (unsigned long long)bucket;
            ctrl[0] = need - gt;
            ctrl[1] = hist[bucket];
        }
        __syncthreads();
        if (mode == 1) {
            unsigned bucket = ctrl[2];
            if (tid == 0) ctrl[3] = 0;
            __syncthreads();
            for (unsigned j = tid; j < C; j += 1024) {
                unsigned long long key = csrc[j];
                if ((unsigned)((key >> sh) & dmask) == bucket)
                    cdst[atomicAdd(&ctrl[3], 1u)] = key;
            }
            __syncthreads();
            C = ctrl[1];
            unsigned long long* t = csrc; csrc = cdst; cdst = t;
        }
    }
    if (!have_T) T64 = *s_pref;   // full 64-bit key of the boundary element
    __syncthreads();

    // final compaction: exactly 1000 keys >= T64
    if (tid == 0) ctrl[3] = 0;
    __syncthreads();
    #pragma unroll
    for (int it = 0; it < 25; ++it) {
        int i = tid + it * 1024;
        if (i < NANCH) {
            unsigned long long key =
                ((unsigned long long)enc[i] << 32) | (unsigned)(~(unsigned)i);
            if (key >= T64) {
                unsigned pos = atomicAdd(&ctrl[3], 1u);
                if (pos < KPAD) outk[pos] = key;
            }
        }
    }
    __syncthreads();
    unsigned cnt = ctrl[3];
    if (tid >= (int)cnt) outk[tid] = 0ull;
    __syncthreads();

    // bitonic sort 1024 descending
    for (unsigned kk = 2; kk <= 1024; kk <<= 1) {
        for (unsigned j = kk >> 1; j > 0; j >>= 1) {
            unsigned i = (unsigned)tid, ixj = i ^ j;
            if (ixj > i) {
                unsigned long long a = outk[i], bb = outk[ixj];
                bool desc = ((i & kk) == 0);
                if (desc ? (a < bb) : (a > bb)) { outk[i] = bb; outk[ixj] = a; }
            }
            __syncthreads();
        }
    }

    if (tid < TOPK) {
        unsigned long long key = outk[tid];
        unsigned e = (unsigned)(key >> 32);
        unsigned u = (e & 0x80000000u) ? (e ^ 0x80000000u) : ~e;
        g_topscore[b * KPAD + tid] = __uint_as_float(u);
        g_topidx[b * KPAD + tid]   = (int)(~(unsigned)(key & 0xffffffffull));
    } else {
        g_topscore[b * KPAD + tid] = -1.0f;
        g_topidx[b * KPAD + tid]   = 0;
    }
}

// ---------------- K3a: gather boxes, xywh->xyxy, offsets, areas; pad to KPAD ----------------
__global__ void k_boxes(const float* __restrict__ x) {
    int t = blockIdx.x * blockDim.x + threadIdx.x;
    if (t >= BATCH * KPAD) return;
    int b = t >> 10, r = t & (KPAD - 1);
    if (r >= TOPK) {   // pad: degenerate point box at origin -> IoU 0 vs anything
        g_boxk[t] = make_float4(0.f, 0.f, 0.f, 0.f);
        g_offk[t] = make_float4(0.f, 0.f, 0.f, 0.f);
        g_area[t] = 0.f; g_clsf[t] = 0.f;
        return;
    }
    int idx = g_topidx[b * KPAD + r];
    const float* p = x + ((size_t)b * NANCH + idx) * NCH;
    float cx = p[0], cy = p[1], w = p[2], h = p[3];
    float hw = __fmul_rn(w, 0.5f), hh = __fmul_rn(h, 0.5f);
    float x1 = __fsub_rn(cx, hw), y1 = __fsub_rn(cy, hh);
    float x2 = __fadd_rn(cx, hw), y2 = __fadd_rn(cy, hh);
    float cf = (float)g_cls[b * NANCH + idx];
    float o  = __fmul_rn(cf, MAX_WH);
    float ox1 = __fadd_rn(x1, o), oy1 = __fadd_rn(y1, o);
    float ox2 = __fadd_rn(x2, o), oy2 = __fadd_rn(y2, o);
    g_boxk[t] = make_float4(x1, y1, x2, y2);
    g_offk[t] = make_float4(ox1, oy1, ox2, oy2);
    g_area[t] = __fmul_rn(__fsub_rn(ox2, ox1), __fsub_rn(oy2, oy1));
    g_clsf[t] = cf;
}

// ---------------- K3b: IoU bit matrix; smem-staged, 4-row register blocking ----------------
__global__ void __launch_bounds__(256) k_iou() {
    __shared__ float4 sbox[KPAD];
    __shared__ float  sarea[KPAD];
    const int b       = blockIdx.x >> 4;          // 16 blocks per batch
    const int rowbase = (blockIdx.x & 15) * 64;   // 64 rows per block
    const int tid  = threadIdx.x;
    const int warp = tid >> 5, lane = tid & 31;

    #pragma unroll
    for (int q = 0; q < 4; ++q) {
        int j = tid + q * 256;
        sbox[j]  = g_offk[b * KPAD + j];
        sarea[j] = g_area[b * KPAD + j];
    }
    __syncthreads();

    #pragma unroll
    for (int g = 0; g < 2; ++g) {
        int i0 = rowbase + (g * 8 + warp) * 4;
        float4 bi0 = sbox[i0],     bi1 = sbox[i0 + 1];
        float4 bi2 = sbox[i0 + 2], bi3 = sbox[i0 + 3];
        float  a0 = sarea[i0],     a1 = sarea[i0 + 1];
        float  a2 = sarea[i0 + 2], a3 = sarea[i0 + 3];
        unsigned w0 = 0, w1 = 0, w2 = 0, w3 = 0;
        int jbase = lane * 32;
        #pragma unroll 4
        for (int jj = 0; jj < 32; ++jj) {
            float4 bj = sbox[jbase + jj];
            float  aj = sarea[jbase + jj];
            {
                float ww = fmaxf(__fsub_rn(fminf(bi0.z, bj.z), fmaxf(bi0.x, bj.x)), 0.0f);
                float hh = fmaxf(__fsub_rn(fminf(bi0.w, bj.w), fmaxf(bi0.y, bj.y)), 0.0f);
                float inter = __fmul_rn(ww, hh);
                float den = __fadd_rn(__fsub_rn(__fadd_rn(a0, aj), inter), 1e-9f);
                if (__fdiv_rn(inter, den) > IOU_TH) w0 |= (1u << jj);
            }
            {
                float ww = fmaxf(__fsub_rn(fminf(bi1.z, bj.z), fmaxf(bi1.x, bj.x)), 0.0f);
                float hh = fmaxf(__fsub_rn(fminf(bi1.w, bj.w), fmaxf(bi1.y, bj.y)), 0.0f);
                float inter = __fmul_rn(ww, hh);
                float den = __fadd_rn(__fsub_rn(__fadd_rn(a1, aj), inter), 1e-9f);
                if (__fdiv_rn(inter, den) > IOU_TH) w1 |= (1u << jj);
            }
            {
                float ww = fmaxf(__fsub_rn(fminf(bi2.z, bj.z), fmaxf(bi2.x, bj.x)), 0.0f);
                float hh = fmaxf(__fsub_rn(fminf(bi2.w, bj.w), fmaxf(bi2.y, bj.y)), 0.0f);
                float inter = __fmul_rn(ww, hh);
                float den = __fadd_rn(__fsub_rn(__fadd_rn(a2, aj), inter), 1e-9f);
                if (__fdiv_rn(inter, den) > IOU_TH) w2 |= (1u << jj);
            }
            {
                float ww = fmaxf(__fsub_rn(fminf(bi3.z, bj.z), fmaxf(bi3.x, bj.x)), 0.0f);
                float hh = fmaxf(__fsub_rn(fminf(bi3.w, bj.w), fmaxf(bi3.y, bj.y)), 0.0f);
                float inter = __fmul_rn(ww, hh);
                float den = __fadd_rn(__fsub_rn(__fadd_rn(a3, aj), inter), 1e-9f);
                if (__fdiv_rn(inter, den) > IOU_TH) w3 |= (1u << jj);
            }
        }
        // clear diagonal bits
        if ((i0     >> 5) == lane) w0 &= ~(1u << (i0 & 31));
        if (((i0+1) >> 5) == lane) w1 &= ~(1u << ((i0+1) & 31));
        if (((i0+2) >> 5) == lane) w2 &= ~(1u << ((i0+2) & 31));
        if (((i0+3) >> 5) == lane) w3 &= ~(1u << ((i0+3) & 31));
        if (i0     < TOPK) g_bitmat[(b * TOPK + i0    ) * 32 + lane] = w0;
        if (i0 + 1 < TOPK) g_bitmat[(b * TOPK + i0 + 1) * 32 + lane] = w1;
        if (i0 + 2 < TOPK) g_bitmat[(b * TOPK + i0 + 2) * 32 + lane] = w2;
        if (i0 + 3 < TOPK) g_bitmat[(b * TOPK + i0 + 3) * 32 + lane] = w3;
    }
}

// ---------------- K4: windowed sequential greedy scan + output ----------------
#define K4_SMEM ((TOPK * 32 + 64) * 4)
__global__ void __launch_bounds__(1024) k_scan(float* __restrict__ out) {
    const int b   = blockIdx.x;
    const int tid = threadIdx.x;
    extern __shared__ unsigned sm[];
    unsigned* rows  = sm;             // [TOPK*32]
    unsigned* keepw = sm + TOPK * 32; // [32]

    {   // preload bit matrix as uint4 (128 KB)
        const uint4* src = (const uint4*)(g_bitmat + b * TOPK * 32);
        uint4* dst = (uint4*)rows;
        for (int t = tid; t < TOPK * 8; t += 1024) dst[t] = src[t];
    }
    if (tid < 32) keepw[tid] = 0u;
    __syncthreads();

    if (tid < 32) {
        const int lane = tid;
        int V = 0;
        if (lane == 0) {
            int lo = 0, hi = TOPK;
            while (lo < hi) {
                int mid = (lo + hi) >> 1;
                if (g_topscore[b * KPAD + mid] > CONF_TH) lo = mid + 1; else hi = mid;
            }
            V = lo;
        }
        V = __shfl_sync(0xffffffffu, V, 0);
        int nwin = (V + 31) >> 5;
        unsigned supp = 0;   // lane l owns suppression bits for boxes [32l, 32l+32)
        for (int widx = 0; widx < nwin; ++widx) {
            int i0 = widx << 5;
            int lim = V - i0;
            unsigned vmask = (lim >= 32) ? 0xffffffffu : ((1u << lim) - 1u);
            int myrow = i0 + lane;
            unsigned dw = (myrow < TOPK) ? rows[myrow * 32 + widx] : 0u;
            unsigned ext = __shfl_sync(0xffffffffu, supp, widx);
            unsigned sw = ext | ~vmask;   // invalid rows treated as suppressed
            unsigned keep = 0;
            #pragma unroll
            for (int t = 0; t < 32; ++t) {
                unsigned dt = __shfl_sync(0xffffffffu, dw, t);
                if (!((sw >> t) & 1u)) { sw |= dt; keep |= (1u << t); }
            }
            // apply kept rows' suppression to all columns (latency-parallel)
            unsigned acc = 0;
            #pragma unroll
            for (int t = 0; t < 32; ++t) {
                if ((keep >> t) & 1u) acc |= rows[(i0 + t) * 32 + lane];
            }
            supp |= acc;
            if (lane == 0) keepw[widx] = keep;
        }
    }
    __syncthreads();

    for (int r = tid; r < TOPK; r += 1024) {
        bool keep = (keepw[r >> 5] >> (r & 31)) & 1u;
        float4 bx = g_boxk[b * KPAD + r];
        float sc  = g_topscore[b * KPAD + r];
        float cf  = g_clsf[b * KPAD + r];
        if (!keep) { bx = make_float4(0.f, 0.f, 0.f, 0.f); sc = 0.f; cf = 0.f; }
        float* o = out + ((size_t)b * TOPK + r) * 6;
        o[0] = bx.x; o[1] = bx.y; o[2] = bx.z; o[3] = bx.w; o[4] = sc; o[5] = cf;
    }
}

// ---------------- launcher ----------------
extern "C" void kernel_launch(void* const* d_in, const int* in_sizes, int n_in,
                              void* d_out, int out_size) {
    (void)in_sizes; (void)n_in; (void)out_size;
    const float* x = (const float*)d_in[0];
    float* out = (float*)d_out;
    cudaFuncSetAttribute(k_topk, cudaFuncAttributeMaxDynamicSharedMemorySize, K2_SMEM);
    cudaFuncSetAttribute(k_scan, cudaFuncAttributeMaxDynamicSharedMemorySize, K4_SMEM);

    k_score<<<(BATCH * NANCH) / 8, 256>>>(x);
    k_topk <<<BATCH, 1024, K2_SMEM>>>();
    k_boxes<<<(BATCH * KPAD + 255) / 256, 256>>>(x);
    k_iou  <<<BATCH * 16, 256>>>();
    k_scan <<<BATCH, 1024, K4_SMEM>>>(out);
}

// round 3
// speedup vs baseline: 1.7416x; 1.4947x over previous
#include <cuda_runtime.h>
#include <cstdint>

#define BATCH   8
#define NANCH   25200
#define NCH     85
#define TOPK    1000
#define KPAD    1024
#define NCLS    80
#define CONF_TH 0.25f
#define IOU_TH  0.45f
#define MAX_WH  4096.0f
#define CAP     2048
#define RSTR    33   // bitmat row stride in words (33 -> conflict-free column access)

// ---------------- scratch (device globals; no allocation) ----------------
__device__ float    g_score[BATCH * NANCH];
__device__ int      g_cls[BATCH * NANCH];
__device__ int      g_topidx[BATCH * KPAD];
__device__ float    g_topscore[BATCH * KPAD];

// ---------------- K1: score = obj * max(cls), masked; argmax class ----------------
__global__ void k_score(const float* __restrict__ x) {
    int a    = blockIdx.x * 8 + (threadIdx.x >> 5);
    int lane = threadIdx.x & 31;
    const float* p = x + (size_t)a * NCH;
    float v0 = p[lane];
    float v1 = p[32 + lane];
    float v2 = (lane < 21) ? p[64 + lane] : 0.0f;
    float obj = __shfl_sync(0xffffffffu, v0, 4);

    float best = __int_as_float(0xff800000);
    int   bi   = 1 << 30;
    if (lane >= 5)              { best = v0; bi = lane - 5;  }
    if (v1 > best)              { best = v1; bi = 27 + lane; }
    if (lane < 21 && v2 > best) { best = v2; bi = 59 + lane; }
    #pragma unroll
    for (int off = 16; off; off >>= 1) {
        float ov = __shfl_down_sync(0xffffffffu, best, off);
        int   oi = __shfl_down_sync(0xffffffffu, bi, off);
        if (ov > best || (ov == best && oi < bi)) { best = ov; bi = oi; }
    }
    if (lane == 0) {
        float sc = __fmul_rn(obj, best);
        g_score[a] = (sc > CONF_TH) ? sc : -1.0f;
        g_cls[a]   = bi;
    }
}

// ---------------- K2: exact top-1000 per batch (11-bit radix + compaction) ----------------
#define SM_CAND   0
#define SM_CAND2  16384
#define SM_OUTK   32768
#define SM_PREFIX 40960
#define SM_ENC    40968
#define SM_HIST   141768
#define SM_SCN    149960
#define SM_CTRL   158152
#define K2_SMEM   158200

__global__ void __launch_bounds__(1024) k_topk() {
    const int b   = blockIdx.x;
    const int tid = threadIdx.x;
    extern __shared__ unsigned char smraw[];
    unsigned long long* cand   = (unsigned long long*)(smraw + SM_CAND);
    unsigned long long* cand2  = (unsigned long long*)(smraw + SM_CAND2);
    unsigned long long* outk   = (unsigned long long*)(smraw + SM_OUTK);
    unsigned long long* s_pref = (unsigned long long*)(smraw + SM_PREFIX);
    unsigned*           enc    = (unsigned*)(smraw + SM_ENC);
    unsigned*           hist   = (unsigned*)(smraw + SM_HIST);
    unsigned*           scn    = (unsigned*)(smraw + SM_SCN);
    unsigned*           ctrl   = (unsigned*)(smraw + SM_CTRL);

    const int shifts_[6] = {53, 42, 31, 20, 9, 0};
    const int widths_[6] = {11, 11, 11, 11, 11, 9};

    if (tid == 0) { *s_pref = 0ull; ctrl[0] = TOPK; ctrl[1] = NANCH; }
    __syncthreads();

    int mode = 0;
    unsigned C = 0;
    unsigned long long T64 = 0;
    int have_T = 0;
    unsigned long long* csrc = cand;
    unsigned long long* cdst = cand2;

    for (int lev = 0; lev < 6; ++lev) {
        unsigned need = ctrl[0], count = ctrl[1];
        unsigned long long prefix = *s_pref;
        if (lev > 0) {
            int psh = shifts_[lev - 1];
            if (need == count) { T64 = prefix << psh; have_T = 1; break; }
            if (mode == 0 && count <= CAP) {
                if (tid == 0) ctrl[3] = 0;
                __syncthreads();
                #pragma unroll
                for (int it = 0; it < 25; ++it) {
                    int i = tid + it * 1024;
                    if (i < NANCH) {
                        unsigned long long key =
                            ((unsigned long long)enc[i] << 32) | (unsigned)(~(unsigned)i);
                        if ((key >> psh) == prefix) {
                            unsigned pos = atomicAdd(&ctrl[3], 1u);
                            if (pos < CAP) cand[pos] = key;
                        }
                    }
                }
                __syncthreads();
                C = count; mode = 1; csrc = cand; cdst = cand2;
            }
        }
        int sh = shifts_[lev], wd = widths_[lev];
        unsigned dmask = (1u << wd) - 1u;
        int psh = (lev > 0) ? shifts_[lev - 1] : 0;

        hist[tid] = 0u; hist[tid + 1024] = 0u;
        __syncthreads();

        if (mode == 1) {
            for (unsigned j = tid; j < C; j += 1024) {
                unsigned d = (unsigned)((csrc[j] >> sh) & dmask);
                atomicAdd(&hist[d], 1u);
            }
        } else {
            #pragma unroll
            for (int it = 0; it < 25; ++it) {
                int i = tid + it * 1024;
                unsigned d = 0xffffffffu;
                if (i < NANCH) {
                    unsigned e;
                    if (lev == 0) {
                        unsigned u = __float_as_uint(g_score[b * NANCH + i]);
                        e = (u & 0x80000000u) ? ~u : (u | 0x80000000u);
                        enc[i] = e;
                        d = e >> 21;
                    } else {
                        e = enc[i];
                        unsigned long long key =
                            ((unsigned long long)e << 32) | (unsigned)(~(unsigned)i);
                        if ((key >> psh) == prefix)
                            d = (unsigned)((key >> sh) & dmask);
                    }
                }
                unsigned mm = __match_any_sync(0xffffffffu, d);
                if (d != 0xffffffffu) {
                    if ((tid & 31) == (__ffs(mm) - 1))
                        atomicAdd(&hist[d], (unsigned)__popc(mm));
                }
            }
        }
        __syncthreads();

        scn[tid] = hist[tid]; scn[tid + 1024] = hist[tid + 1024];
        __syncthreads();
        for (int d = 1; d < 2048; d <<= 1) {
            unsigned v0 = (tid + d < 2048) ? scn[tid + d] : 0u;
            unsigned v1 = (tid + 1024 + d < 2048) ? scn[tid + 1024 + d] : 0u;
            __syncthreads();
            scn[tid] += v0; scn[tid + 1024] += v1;
            __syncthreads();
        }
        #pragma unroll
        for (int q = 0; q < 2; ++q) {
            int d = tid + q * 1024;
            unsigned tot = scn[d], gt = tot - hist[d];
            if (gt < need && need <= tot) ctrl[2] = (unsigned)d;
        }
        __syncthreads();
        if (tid == 0) {
            unsigned bucket = ctrl[2];
            unsigned gt = scn[bucket] - hist[bucket];
            *s_pref = (prefix << wd) | (unsigned long long)bucket;
            ctrl[0] = need - gt;
            ctrl[1] = hist[bucket];
        }
        __syncthreads();
        if (mode == 1) {
            unsigned bucket = ctrl[2];
            if (tid == 0) ctrl[3] = 0;
            __syncthreads();
            for (unsigned j = tid; j < C; j += 1024) {
                unsigned long long key = csrc[j];
                if ((unsigned)((key >> sh) & dmask) == bucket)
                    cdst[atomicAdd(&ctrl[3], 1u)] = key;
            }
            __syncthreads();
            C = ctrl[1];
            unsigned long long* t = csrc; csrc = cdst; cdst = t;
        }
    }
    if (!have_T) T64 = *s_pref;
    __syncthreads();

    if (tid == 0) ctrl[3] = 0;
    __syncthreads();
    #pragma unroll
    for (int it = 0; it < 25; ++it) {
        int i = tid + it * 1024;
        if (i < NANCH) {
            unsigned long long key =
                ((unsigned long long)enc[i] << 32) | (unsigned)(~(unsigned)i);
            if (key >= T64) {
                unsigned pos = atomicAdd(&ctrl[3], 1u);
                if (pos < KPAD) outk[pos] = key;
            }
        }
    }
    __syncthreads();
    unsigned cnt = ctrl[3];
    if (tid >= (int)cnt) outk[tid] = 0ull;
    __syncthreads();

    for (unsigned kk = 2; kk <= 1024; kk <<= 1) {
        for (unsigned j = kk >> 1; j > 0; j >>= 1) {
            unsigned i = (unsigned)tid, ixj = i ^ j;
            if (ixj > i) {
                unsigned long long a = outk[i], bb = outk[ixj];
                bool desc = ((i & kk) == 0);
                if (desc ? (a < bb) : (a > bb)) { outk[i] = bb; outk[ixj] = a; }
            }
            __syncthreads();
        }
    }

    if (tid < TOPK) {
        unsigned long long key = outk[tid];
        unsigned e = (unsigned)(key >> 32);
        unsigned u = (e & 0x80000000u) ? (e ^ 0x80000000u) : ~e;
        g_topscore[b * KPAD + tid] = __uint_as_float(u);
        g_topidx[b * KPAD + tid]   = (int)(~(unsigned)(key & 0xffffffffull));
    } else {
        g_topscore[b * KPAD + tid] = -1.0f;
        g_topidx[b * KPAD + tid]   = 0;
    }
}

// ---------------- K3: fused gather + class-sparse IoU + greedy scan + output ----------------
// Different classes cannot overlap (4096*dc offset >> box extent) => iou exactly 0.
// Only same-class pairs are computed with the reference fp32 arithmetic.
#define PO_ROWS   0                                   // unsigned[KPAD*RSTR]
#define PO_BOXO   (PO_ROWS + KPAD * RSTR * 4)         // float4[KPAD]
#define PO_BOXP   (PO_BOXO + KPAD * 16)               // float4[KPAD]
#define PO_AREA   (PO_BOXP + KPAD * 16)               // float [KPAD]
#define PO_SCORE  (PO_AREA + KPAD * 4)                // float [KPAD]
#define PO_CLSF   (PO_SCORE + KPAD * 4)               // float [KPAD]
#define PO_CLSI   (PO_CLSF + KPAD * 4)                // int   [KPAD]
#define PO_CLIST  (PO_CLSI + KPAD * 4)                // int   [KPAD]
#define PO_CBASE  (PO_CLIST + KPAD * 4)               // int   [NCLS+1]
#define PO_COFF   (PO_CBASE + 512)                    // int   [NCLS]
#define PO_KEEPW  (PO_COFF + 512)                     // unsigned[32]
#define K3_SMEM   (PO_KEEPW + 128)

__global__ void __launch_bounds__(1024) k_post(const float* __restrict__ x,
                                               float* __restrict__ out) {
    const int b   = blockIdx.x;
    const int tid = threadIdx.x;
    extern __shared__ unsigned char sm[];
    unsigned* rows  = (unsigned*)(sm + PO_ROWS);
    float4*   boxo  = (float4*)  (sm + PO_BOXO);
    float4*   boxp  = (float4*)  (sm + PO_BOXP);
    float*    area  = (float*)   (sm + PO_AREA);
    float*    score = (float*)   (sm + PO_SCORE);
    float*    clsf  = (float*)   (sm + PO_CLSF);
    int*      clsi  = (int*)     (sm + PO_CLSI);
    int*      clist = (int*)     (sm + PO_CLIST);
    int*      cbase = (int*)     (sm + PO_CBASE);
    int*      coff  = (int*)     (sm + PO_COFF);
    unsigned* keepw = (unsigned*)(sm + PO_KEEPW);

    // zero bitmat (33 words per row; word 32 unused pad)
    for (int t = tid; t < KPAD * RSTR; t += 1024) rows[t] = 0u;
    if (tid < NCLS)  coff[tid] = 0;          // class counters
    if (tid < 32)    keepw[tid] = 0u;

    // gather
    float sc = g_topscore[b * KPAD + tid];
    score[tid] = sc;
    int c = -1;
    if (tid < TOPK) {
        int idx = g_topidx[b * KPAD + tid];
        const float* p = x + ((size_t)b * NANCH + idx) * NCH;
        float cx = p[0], cy = p[1], w = p[2], h = p[3];
        float hw = __fmul_rn(w, 0.5f), hh = __fmul_rn(h, 0.5f);
        float x1 = __fsub_rn(cx, hw), y1 = __fsub_rn(cy, hh);
        float x2 = __fadd_rn(cx, hw), y2 = __fadd_rn(cy, hh);
        c = g_cls[b * NANCH + idx];
        float cf = (float)c;
        float o  = __fmul_rn(cf, MAX_WH);
        float ox1 = __fadd_rn(x1, o), oy1 = __fadd_rn(y1, o);
        float ox2 = __fadd_rn(x2, o), oy2 = __fadd_rn(y2, o);
        boxp[tid] = make_float4(x1, y1, x2, y2);
        boxo[tid] = make_float4(ox1, oy1, ox2, oy2);
        area[tid] = __fmul_rn(__fsub_rn(ox2, ox1), __fsub_rn(oy2, oy1));
        clsf[tid] = cf;
    } else {
        boxp[tid] = make_float4(0.f, 0.f, 0.f, 0.f);
        boxo[tid] = make_float4(0.f, 0.f, 0.f, 0.f);
        area[tid] = 0.f; clsf[tid] = 0.f;
    }
    clsi[tid] = c;
    int V = __syncthreads_count(tid < TOPK && sc > CONF_TH);   // valid prefix length

    // counting sort by class
    if (tid < TOPK) atomicAdd(&coff[c], 1);
    __syncthreads();
    if (tid == 0) {
        int run = 0;
        #pragma unroll
        for (int k = 0; k < NCLS; ++k) { cbase[k] = run; run += coff[k]; }
        cbase[NCLS] = run;
    }
    __syncthreads();
    if (tid < NCLS) coff[tid] = cbase[tid];
    __syncthreads();
    if (tid < TOPK) clist[atomicAdd(&coff[c], 1)] = tid;
    __syncthreads();

    // sparse IoU: thread t owns row t, iterates its class bucket
    if (tid < TOPK) {
        float4 bi = boxo[tid];
        float  ai = area[tid];
        int k0 = cbase[c], k1 = cbase[c + 1];
        for (int k = k0; k < k1; ++k) {
            int j = clist[k];
            if (j == tid) continue;
            float4 bj = boxo[j];
            float ww = fmaxf(__fsub_rn(fminf(bi.z, bj.z), fmaxf(bi.x, bj.x)), 0.0f);
            float hh = fmaxf(__fsub_rn(fminf(bi.w, bj.w), fmaxf(bi.y, bj.y)), 0.0f);
            float inter = __fmul_rn(ww, hh);
            float den = __fadd_rn(__fsub_rn(__fadd_rn(ai, area[j]), inter), 1e-9f);
            if (__fdiv_rn(inter, den) > IOU_TH)
                rows[tid * RSTR + (j >> 5)] |= (1u << (j & 31));
        }
    }
    __syncthreads();

    // windowed greedy scan (warp 0)
    if (tid < 32) {
        const int lane = tid;
        int nwin = (V + 31) >> 5;
        unsigned supp = 0;   // lane l owns suppression bits for boxes [32l, 32l+32)
        for (int widx = 0; widx < nwin; ++widx) {
            int i0 = widx << 5;
            int lim = V - i0;
            unsigned vmask = (lim >= 32) ? 0xffffffffu : ((1u << lim) - 1u);
            unsigned dw = rows[(i0 + lane) * RSTR + widx];
            unsigned ext = __shfl_sync(0xffffffffu, supp, widx);
            unsigned sw = ext | ~vmask;
            unsigned keep = 0;
            #pragma unroll
            for (int t = 0; t < 32; ++t) {
                unsigned dt = __shfl_sync(0xffffffffu, dw, t);
                if (!((sw >> t) & 1u)) { sw |= dt; keep |= (1u << t); }
            }
            unsigned acc = 0;
            #pragma unroll
            for (int t = 0; t < 32; ++t) {
                if ((keep >> t) & 1u) acc |= rows[(i0 + t) * RSTR + lane];
            }
            supp |= acc;
            if (lane == 0) keepw[widx] = keep;
        }
    }
    __syncthreads();

    // output
    if (tid < TOPK) {
        bool keep = (keepw[tid >> 5] >> (tid & 31)) & 1u;
        float4 bx = boxp[tid];
        float so  = score[tid];
        float cf  = clsf[tid];
        if (!keep) { bx = make_float4(0.f, 0.f, 0.f, 0.f); so = 0.f; cf = 0.f; }
        float* o = out + ((size_t)b * TOPK + tid) * 6;
        o[0] = bx.x; o[1] = bx.y; o[2] = bx.z; o[3] = bx.w; o[4] = so; o[5] = cf;
    }
}

// ---------------- launcher ----------------
extern "C" void kernel_launch(void* const* d_in, const int* in_sizes, int n_in,
                              void* d_out, int out_size) {
    (void)in_sizes; (void)n_in; (void)out_size;
    const float* x = (const float*)d_in[0];
    float* out = (float*)d_out;
    cudaFuncSetAttribute(k_topk, cudaFuncAttributeMaxDynamicSharedMemorySize, K2_SMEM);
    cudaFuncSetAttribute(k_post, cudaFuncAttributeMaxDynamicSharedMemorySize, K3_SMEM);

    k_score<<<(BATCH * NANCH) / 8, 256>>>(x);
    k_topk <<<BATCH, 1024, K2_SMEM>>>();
    k_post <<<BATCH, 1024, K3_SMEM>>>(x, out);
}

// round 4
// speedup vs baseline: 1.8170x; 1.0433x over previous
#include <cuda_runtime.h>
#include <cstdint>

#define BATCH   8
#define NANCH   25200
#define NCH     85
#define TOPK    1000
#define KPAD    1024
#define NCLS    80
#define CONF_TH 0.25f
#define IOU_TH  0.45f
#define MAX_WH  4096.0f
#define CAPG    8192
#define RSTR    33
#define NB12    4096   // 12-bit level-0 buckets

// ---------------- scratch (device globals; no allocation) ----------------
__device__ unsigned           g_enc [BATCH * NANCH];
__device__ int                g_cls [BATCH * NANCH];
__device__ unsigned           g_hist[BATCH * NB12];    // zeroed by k_pick after use
__device__ unsigned long long g_cand[BATCH * CAPG];
__device__ unsigned long long g_sel [BATCH * KPAD];
__device__ unsigned           g_ccnt[BATCH];           // zeroed by k_sel after use
__device__ unsigned           g_scnt[BATCH];           // zeroed by k_post after use
__device__ unsigned           g_bucket[BATCH];
__device__ unsigned           g_need[BATCH];
__device__ unsigned long long g_T64[BATCH];

// ---------------- K1: thread-per-anchor score/argmax + fused 12-bit histogram ----------------
#define SB_ANCH 128
__global__ void __launch_bounds__(SB_ANCH) k_score(const float* __restrict__ x) {
    __shared__ float sx[SB_ANCH * NCH];   // 43520 B
    const int tid = threadIdx.x;
    const size_t base = (size_t)blockIdx.x * SB_ANCH * NCH;
    #pragma unroll
    for (int t = tid; t < SB_ANCH * NCH; t += SB_ANCH) sx[t] = x[base + t];
    __syncthreads();

    const int a = blockIdx.x * SB_ANCH + tid;           // global anchor id
    const float* p = sx + tid * NCH;
    float obj = p[4];
    float best = p[5];
    int   bi   = 0;
    #pragma unroll 8
    for (int c = 1; c < NCLS; ++c) {
        float v = p[5 + c];
        bool gt = v > best;                 // strict > keeps lowest index on ties
        best = gt ? v : best;
        bi   = gt ? c : bi;
    }
    float sc = __fmul_rn(obj, best);
    unsigned u = __float_as_uint((sc > CONF_TH) ? sc : -1.0f);
    unsigned e = (u & 0x80000000u) ? ~u : (u | 0x80000000u);
    g_enc[a] = e;
    g_cls[a] = bi;

    int b = a / NANCH;
    unsigned addr = (unsigned)b * NB12 + (e >> 20);
    unsigned mm = __match_any_sync(0xffffffffu, addr);  // warp-aggregate (masked -1s collide)
    if ((tid & 31) == (__ffs(mm) - 1))
        atomicAdd(&g_hist[addr], (unsigned)__popc(mm));
}

// ---------------- K2a: pick boundary bucket per batch; re-zero hist ----------------
__global__ void __launch_bounds__(1024) k_pick() {
    const int b = blockIdx.x, tid = threadIdx.x;
    __shared__ unsigned h[NB12], s[NB12];
    #pragma unroll
    for (int q = 0; q < 4; ++q) {
        int i = tid + q * 1024;
        unsigned v = g_hist[b * NB12 + i];
        h[i] = v; s[i] = v;
        g_hist[b * NB12 + i] = 0u;          // self-clean for next replay
    }
    __syncthreads();
    for (int d = 1; d < NB12; d <<= 1) {    // inclusive suffix sum
        unsigned v[4];
        #pragma unroll
        for (int q = 0; q < 4; ++q) {
            int i = tid + q * 1024;
            v[q] = (i + d < NB12) ? s[i + d] : 0u;
        }
        __syncthreads();
        #pragma unroll
        for (int q = 0; q < 4; ++q) s[tid + q * 1024] += v[q];
        __syncthreads();
    }
    #pragma unroll
    for (int q = 0; q < 4; ++q) {
        int i = tid + q * 1024;
        unsigned tot = s[i], gt = tot - h[i];
        if (gt < TOPK && TOPK <= tot) {
            g_bucket[b] = (unsigned)i;
            g_need[b]   = TOPK - gt;
        }
    }
}

// ---------------- K2b: compact boundary-bucket candidates (grid-wide) ----------------
__global__ void __launch_bounds__(1024) k_cand() {
    const int b = blockIdx.y;
    const int i = blockIdx.x * 1024 + threadIdx.x;
    if (i >= NANCH) return;
    unsigned e = g_enc[b * NANCH + i];
    if ((e >> 20) == g_bucket[b]) {
        unsigned pos = atomicAdd(&g_ccnt[b], 1u);
        if (pos < CAPG)
            g_cand[b * CAPG + pos] =
                ((unsigned long long)e << 32) | (unsigned)(~(unsigned)i);
    }
}

// ---------------- K2c: radix-select exact 1000th key within candidates ----------------
#define SEL_CAND  0
#define SEL_CAND2 65536
#define SEL_HIST  131072
#define SEL_SCN   139264
#define SEL_CTRL  147456
#define SEL_SMEM  147488
__global__ void __launch_bounds__(1024) k_sel() {
    const int b = blockIdx.x, tid = threadIdx.x;
    extern __shared__ unsigned char smraw[];
    unsigned long long* cbufA = (unsigned long long*)(smraw + SEL_CAND);
    unsigned long long* cbufB = (unsigned long long*)(smraw + SEL_CAND2);
    unsigned* hist = (unsigned*)(smraw + SEL_HIST);
    unsigned* scn  = (unsigned*)(smraw + SEL_SCN);
    unsigned* ctrl = (unsigned*)(smraw + SEL_CTRL);

    unsigned M0 = g_ccnt[b];
    unsigned C  = (M0 < CAPG) ? M0 : CAPG;
    unsigned need = g_need[b];
    unsigned long long prefix = (unsigned long long)g_bucket[b];
    for (unsigned j = tid; j < C; j += 1024) cbufA[j] = g_cand[b * CAPG + j];
    __syncthreads();

    const int shifts_[5] = {41, 30, 19, 8, 0};
    const int widths_[5] = {11, 11, 11, 11, 8};

    unsigned long long T64 = 0;
    bool done = false;
    if (need == C) { T64 = prefix << 52; done = true; }

    unsigned long long* csrc = cbufA;
    unsigned long long* cdst = cbufB;
    for (int lev = 0; lev < 5 && !done; ++lev) {
        int sh = shifts_[lev], wd = widths_[lev];
        unsigned dmask = (1u << wd) - 1u;
        hist[tid] = 0u; hist[tid + 1024] = 0u;
        __syncthreads();
        for (unsigned j = tid; j < C; j += 1024)
            atomicAdd(&hist[(unsigned)((csrc[j] >> sh) & dmask)], 1u);
        __syncthreads();
        scn[tid] = hist[tid]; scn[tid + 1024] = hist[tid + 1024];
        __syncthreads();
        for (int d = 1; d < 2048; d <<= 1) {
            unsigned v0 = (tid + d < 2048) ? scn[tid + d] : 0u;
            unsigned v1 = (tid + 1024 + d < 2048) ? scn[tid + 1024 + d] : 0u;
            __syncthreads();
            scn[tid] += v0; scn[tid + 1024] += v1;
            __syncthreads();
        }
        #pragma unroll
        for (int q = 0; q < 2; ++q) {
            int d = tid + q * 1024;
            unsigned tot = scn[d], gt = tot - hist[d];
            if (gt < need && need <= tot) ctrl[0] = (unsigned)d;
        }
        if (tid == 0) ctrl[1] = 0u;
        __syncthreads();
        unsigned bucket = ctrl[0];
        unsigned gt = scn[bucket] - hist[bucket];
        unsigned cnt = hist[bucket];
        for (unsigned j = tid; j < C; j += 1024) {
            unsigned long long key = csrc[j];
            if ((unsigned)((key >> sh) & dmask) == bucket)
                cdst[atomicAdd(&ctrl[1], 1u)] = key;
        }
        __syncthreads();
        prefix = (prefix << wd) | (unsigned long long)bucket;
        need -= gt;
        C = cnt;
        { unsigned long long* t = csrc; csrc = cdst; cdst = t; }
        if (need == C) { T64 = prefix << sh; done = true; }
    }
    if (!done) T64 = prefix;
    if (tid == 0) { g_T64[b] = T64; g_ccnt[b] = 0u; }   // self-clean
}

// ---------------- K2d: collect the exactly-1000 keys >= T64 (grid-wide) ----------------
__global__ void __launch_bounds__(1024) k_coll() {
    const int b = blockIdx.y;
    const int i = blockIdx.x * 1024 + threadIdx.x;
    if (i >= NANCH) return;
    unsigned e = g_enc[b * NANCH + i];
    unsigned long long key = ((unsigned long long)e << 32) | (unsigned)(~(unsigned)i);
    if (key >= g_T64[b]) {
        unsigned pos = atomicAdd(&g_scnt[b], 1u);
        if (pos < KPAD) g_sel[b * KPAD + pos] = key;
    }
}

// ---------------- K3: fused sort + gather + class-sparse IoU + greedy scan + output ----------------
#define PO_ROWS   0
#define PO_BOXO   (PO_ROWS + KPAD * RSTR * 4)
#define PO_BOXP   (PO_BOXO + KPAD * 16)
#define PO_AREA   (PO_BOXP + KPAD * 16)
#define PO_SCORE  (PO_AREA + KPAD * 4)
#define PO_CLSF   (PO_SCORE + KPAD * 4)
#define PO_CLSI   (PO_CLSF + KPAD * 4)
#define PO_CLIST  (PO_CLSI + KPAD * 4)
#define PO_CBASE  (PO_CLIST + KPAD * 4)
#define PO_COFF   (PO_CBASE + 512)
#define PO_KEEPW  (PO_COFF + 512)
#define PO_OUTK   (PO_KEEPW + 128)
#define K3_SMEM   (PO_OUTK + KPAD * 8)

__global__ void __launch_bounds__(1024) k_post(const float* __restrict__ x,
                                               float* __restrict__ out) {
    const int b   = blockIdx.x;
    const int tid = threadIdx.x;
    extern __shared__ unsigned char sm[];
    unsigned* rows  = (unsigned*)(sm + PO_ROWS);
    float4*   boxo  = (float4*)  (sm + PO_BOXO);
    float4*   boxp  = (float4*)  (sm + PO_BOXP);
    float*    area  = (float*)   (sm + PO_AREA);
    float*    score = (float*)   (sm + PO_SCORE);
    float*    clsf  = (float*)   (sm + PO_CLSF);
    int*      clsi  = (int*)     (sm + PO_CLSI);
    int*      clist = (int*)     (sm + PO_CLIST);
    int*      cbase = (int*)     (sm + PO_CBASE);
    int*      coff  = (int*)     (sm + PO_COFF);
    unsigned* keepw = (unsigned*)(sm + PO_KEEPW);
    unsigned long long* outk = (unsigned long long*)(sm + PO_OUTK);

    // load selected keys and sort (bitonic, desc) -- zeros pad to the tail
    unsigned n = g_scnt[b];
    outk[tid] = (tid < n) ? g_sel[b * KPAD + tid] : 0ull;
    __syncthreads();
    for (unsigned kk = 2; kk <= 1024; kk <<= 1) {
        for (unsigned j = kk >> 1; j > 0; j >>= 1) {
            unsigned i = (unsigned)tid, ixj = i ^ j;
            if (ixj > i) {
                unsigned long long a = outk[i], bb = outk[ixj];
                bool desc = ((i & kk) == 0);
                if (desc ? (a < bb) : (a > bb)) { outk[i] = bb; outk[ixj] = a; }
            }
            __syncthreads();
        }
    }

    // zero bitmat + counters
    for (int t = tid; t < KPAD * RSTR; t += 1024) rows[t] = 0u;
    if (tid < NCLS) coff[tid] = 0;
    if (tid < 32)   keepw[tid] = 0u;

    // decode + gather
    unsigned long long key = outk[tid];
    float sc = -1.0f;
    int   idx = 0;
    if (key != 0ull) {
        unsigned e = (unsigned)(key >> 32);
        unsigned u = (e & 0x80000000u) ? (e ^ 0x80000000u) : ~e;
        sc = __uint_as_float(u);
        idx = (int)(~(unsigned)(key & 0xffffffffull));
    }
    score[tid] = sc;
    int c = -1;
    if (tid < TOPK && key != 0ull) {
        const float* p = x + ((size_t)b * NANCH + idx) * NCH;
        float cx = p[0], cy = p[1], w = p[2], h = p[3];
        float hw = __fmul_rn(w, 0.5f), hh = __fmul_rn(h, 0.5f);
        float x1 = __fsub_rn(cx, hw), y1 = __fsub_rn(cy, hh);
        float x2 = __fadd_rn(cx, hw), y2 = __fadd_rn(cy, hh);
        c = g_cls[b * NANCH + idx];
        float cf = (float)c;
        float o  = __fmul_rn(cf, MAX_WH);
        float ox1 = __fadd_rn(x1, o), oy1 = __fadd_rn(y1, o);
        float ox2 = __fadd_rn(x2, o), oy2 = __fadd_rn(y2, o);
        boxp[tid] = make_float4(x1, y1, x2, y2);
        boxo[tid] = make_float4(ox1, oy1, ox2, oy2);
        area[tid] = __fmul_rn(__fsub_rn(ox2, ox1), __fsub_rn(oy2, oy1));
        clsf[tid] = cf;
    } else {
        boxp[tid] = make_float4(0.f, 0.f, 0.f, 0.f);
        boxo[tid] = make_float4(0.f, 0.f, 0.f, 0.f);
        area[tid] = 0.f; clsf[tid] = 0.f;
    }
    clsi[tid] = c;
    int V = __syncthreads_count(tid < TOPK && sc > CONF_TH);   // valid prefix length

    // counting sort by class (different classes can never overlap: offset >= 4096 >> extent)
    if (c >= 0) atomicAdd(&coff[c], 1);
    __syncthreads();
    if (tid == 0) {
        int run = 0;
        #pragma unroll
        for (int k = 0; k < NCLS; ++k) { cbase[k] = run; run += coff[k]; }
        cbase[NCLS] = run;
    }
    __syncthreads();
    if (tid < NCLS) coff[tid] = cbase[tid];
    __syncthreads();
    if (c >= 0) clist[atomicAdd(&coff[c], 1)] = tid;
    __syncthreads();

    // sparse IoU: only same-class pairs (reference fp32 arithmetic, FMA-free)
    if (c >= 0) {
        float4 bi = boxo[tid];
        float  ai = area[tid];
        int k0 = cbase[c], k1 = cbase[c + 1];
        for (int k = k0; k < k1; ++k) {
            int j = clist[k];
            if (j == tid) continue;
            float4 bj = boxo[j];
            float ww = fmaxf(__fsub_rn(fminf(bi.z, bj.z), fmaxf(bi.x, bj.x)), 0.0f);
            float hh = fmaxf(__fsub_rn(fminf(bi.w, bj.w), fmaxf(bi.y, bj.y)), 0.0f);
            float inter = __fmul_rn(ww, hh);
            float den = __fadd_rn(__fsub_rn(__fadd_rn(ai, area[j]), inter), 1e-9f);
            if (__fdiv_rn(inter, den) > IOU_TH)
                rows[tid * RSTR + (j >> 5)] |= (1u << (j & 31));
        }
    }
    __syncthreads();

    // windowed greedy scan (warp 0)
    if (tid < 32) {
        const int lane = tid;
        int nwin = (V + 31) >> 5;
        unsigned supp = 0;
        for (int widx = 0; widx < nwin; ++widx) {
            int i0 = widx << 5;
            int lim = V - i0;
            unsigned vmask = (lim >= 32) ? 0xffffffffu : ((1u << lim) - 1u);
            unsigned dw = rows[(i0 + lane) * RSTR + widx];
            unsigned ext = __shfl_sync(0xffffffffu, supp, widx);
            unsigned sw = ext | ~vmask;
            unsigned keep = 0;
            #pragma unroll
            for (int t = 0; t < 32; ++t) {
                unsigned dt = __shfl_sync(0xffffffffu, dw, t);
                if (!((sw >> t) & 1u)) { sw |= dt; keep |= (1u << t); }
            }
            unsigned acc = 0;
            #pragma unroll
            for (int t = 0; t < 32; ++t)
                if ((keep >> t) & 1u) acc |= rows[(i0 + t) * RSTR + lane];
            supp |= acc;
            if (lane == 0) keepw[widx] = keep;
        }
    }
    __syncthreads();

    // output
    if (tid < TOPK) {
        bool keep = (keepw[tid >> 5] >> (tid & 31)) & 1u;
        float4 bx = boxp[tid];
        float so  = score[tid];
        float cf  = clsf[tid];
        if (!keep) { bx = make_float4(0.f, 0.f, 0.f, 0.f); so = 0.f; cf = 0.f; }
        float* o = out + ((size_t)b * TOPK + tid) * 6;
        o[0] = bx.x; o[1] = bx.y; o[2] = bx.z; o[3] = bx.w; o[4] = so; o[5] = cf;
    }
    if (tid == 0) g_scnt[b] = 0u;   // self-clean for next replay
}

// ---------------- launcher ----------------
extern "C" void kernel_launch(void* const* d_in, const int* in_sizes, int n_in,
                              void* d_out, int out_size) {
    (void)in_sizes; (void)n_in; (void)out_size;
    const float* x = (const float*)d_in[0];
    float* out = (float*)d_out;
    cudaFuncSetAttribute(k_sel,  cudaFuncAttributeMaxDynamicSharedMemorySize, SEL_SMEM);
    cudaFuncSetAttribute(k_post, cudaFuncAttributeMaxDynamicSharedMemorySize, K3_SMEM);

    k_score<<<(BATCH * NANCH) / SB_ANCH, SB_ANCH>>>(x);
    k_pick <<<BATCH, 1024>>>();
    k_cand <<<dim3(25, BATCH), 1024>>>();
    k_sel  <<<BATCH, 1024, SEL_SMEM>>>();
    k_coll <<<dim3(25, BATCH), 1024>>>();
    k_post <<<BATCH, 1024, K3_SMEM>>>(x, out);
}